// round 11
// baseline (speedup 1.0000x reference)
#include <cuda_runtime.h>
#include <math.h>
#include <stdint.h>

// out = 0.5 * mean(dw * bce) + 0.5 * (1 - max_correct_streak / N)
//   bce_i = -log( (1+eps) - |t_i - p_i| )   (t exactly 0/1)
//   correct_i = (p_i > 0.5) == (t_i > 0.5)
//   dw_i = (i+1)/2^24  -- computed, not loaded.
//
// R11: persistent blocks + rolling cp.async ring. Grid = SMs*4 (one wave,
// 48 KB ring -> 4 blocks/SM). Block b processes chunks {b, b+grid, ...}
// (4096 elems each) through a 6-stage ring; stage g+6 is issued as stage g is
// consumed, so 5-6 load groups stay in flight across chunk boundaries and
// per-chunk reductions -- the per-block drain bubble of R8 is paid once per
// block instead of once per 4096 elems. Each thread owns its private 16 B per
// stream per stage (no cross-thread smem sharing, no pipeline syncs).
// Compute path identical to verified R8. Partials indexed by chunk id ->
// deterministic independent of block/chunk scheduling.

#define FULLMASK 0xFFFFFFFFu

static constexpr int THREADS     = 256;
static constexpr int WARPS       = THREADS / 32;      // 8
static constexpr int CHUNK       = 4096;              // elems per chunk
static constexpr int WARP_ELEMS  = CHUNK / WARPS;     // 512
static constexpr int DEPTH       = 6;                 // ring stages
static constexpr int SLOT_BYTES  = THREADS * 32;      // 8 KB (16 B p + 16 B t per thread)
static constexpr int SMEM_BYTES  = DEPTH * SLOT_BYTES;   // 48 KB dynamic
static constexpr int MAXCHUNKS   = 4096;
static constexpr float EPSF      = 1e-6f;
static constexpr float LN2F      = 0.69314718055994531f;
static constexpr float INV_N     = 1.0f / 16777216.0f;

__device__ float    g_sum[MAXCHUNKS];
__device__ int      g_pref[MAXCHUNKS];
__device__ int      g_mx[MAXCHUNKS];
__device__ int      g_suff[MAXCHUNKS];
__device__ unsigned g_count = 0;   // reset by finishing block each replay

__device__ __forceinline__ void cp_async16(uint32_t smem_addr, const void* gptr) {
    asm volatile("cp.async.cg.shared.global [%0], [%1], 16;"
                 :: "r"(smem_addr), "l"(gptr));
}
__device__ __forceinline__ void cp_commit() {
    asm volatile("cp.async.commit_group;");
}
template <int N>
__device__ __forceinline__ void cp_wait() {
    asm volatile("cp.async.wait_group %0;" :: "n"(N));
}
#define WAIT_AP(ap) do {                       \
    if      ((ap) >= 5) cp_wait<5>();          \
    else if ((ap) == 4) cp_wait<4>();          \
    else if ((ap) == 3) cp_wait<3>();          \
    else if ((ap) == 2) cp_wait<2>();          \
    else if ((ap) == 1) cp_wait<1>();          \
    else                cp_wait<0>(); } while (0)

__device__ __forceinline__ float4 lds128(uint32_t a) {
    float4 v;
    asm volatile("ld.shared.v4.f32 {%0,%1,%2,%3}, [%4];"
                 : "=f"(v.x), "=f"(v.y), "=f"(v.z), "=f"(v.w) : "r"(a));
    return v;
}

__device__ __forceinline__ void seg_combine(int& pref, int& mx, int& suff, int& len,
                                            int prefB, int mxB, int suffB, int lenB) {
    const bool allA = (pref == len);
    const bool allB = (prefB == lenB);
    const int nm = max(max(mx, mxB), suff + prefB);
    const int np = allA ? (len + prefB) : pref;
    const int ns = allB ? (lenB + suff) : suffB;
    pref = np; mx = nm; suff = ns; len += lenB;
}

// Spread low 8 bits: source bit i -> position 4*i.
__device__ __forceinline__ unsigned spread8(unsigned x) {
    unsigned v = x & 0xFFu;
    v = (v | (v << 12)) & 0x000F000Fu;
    v = (v | (v << 6))  & 0x03030303u;
    v = (v | (v << 3))  & 0x11111111u;
    return v;
}

__global__ __launch_bounds__(THREADS, 4)
void fused_kernel(const float* __restrict__ pred,
                  const float* __restrict__ tru,
                  float* __restrict__ out, int n) {
    extern __shared__ __align__(16) char ring[];

    const int tid  = threadIdx.x;
    const int lane = tid & 31;
    const int warp = tid >> 5;
    const int myIt = lane >> 3;     // iteration whose 4 ballots this lane captures

    const uint32_t rb   = (uint32_t)__cvta_generic_to_shared(ring);
    const uint32_t my_p = rb + (uint32_t)(tid * 16);
    const uint32_t my_t = my_p + (uint32_t)(THREADS * 16);

    const int NCH   = n / CHUNK;              // 4096
    const int GRID  = gridDim.x;
    const int b     = blockIdx.x;
    const int count = (NCH - b + GRID - 1) / GRID;  // chunks for this block
    const int T     = count * 4;                    // total stages

    // per-thread fixed offset inside a chunk: warp*512 + stage*128 + lane*4
    const int thrOff = warp * WARP_ELEMS + lane * 4;

    // ---- prologue: fill the ring
    {
        const int pro = T < DEPTH ? T : DEPTH;
        for (int g = 0; g < pro; ++g) {
            const int c = b + (g >> 2) * GRID;
            const size_t goff = (size_t)c * CHUNK + thrOff + (g & 3) * 128;
            const uint32_t so = (uint32_t)(g * SLOT_BYTES);
            cp_async16(my_p + so, pred + goff);
            cp_async16(my_t + so, tru + goff);
            cp_commit();
        }
    }

    __shared__ float s_sum[WARPS];
    __shared__ int s_pref[WARPS], s_mx[WARPS], s_suff[WARPS];

    const float WSTEP = 128.0f * INV_N;
    const float ONEPE = 1.0f + EPSF;

    int slot = 0;
    for (int ci = 0; ci < count; ++ci) {
        const int c = b + ci * GRID;
        float wbar = ((float)(c * CHUNK + thrOff) + 2.5f) * INV_N;
        float sum = 0.0f;
        unsigned r0 = 0, r1 = 0, r2 = 0, r3 = 0;

#pragma unroll
        for (int it = 0; it < 4; ++it) {
            const int g = ci * 4 + it;
            const int ap = T - 1 - g;        // allowed pending groups
            WAIT_AP(ap);

            const uint32_t so = (uint32_t)(slot * SLOT_BYTES);
            const float4 p = lds128(my_p + so);
            const float4 t = lds128(my_t + so);

            const float x0 = ONEPE - fabsf(t.x - p.x);
            const float x1 = ONEPE - fabsf(t.y - p.y);
            const float x2 = ONEPE - fabsf(t.z - p.z);
            const float x3 = ONEPE - fabsf(t.w - p.w);

            const float prod = (x0 * x1) * (x2 * x3);   // >= 1e-24
            sum = fmaf(wbar, __log2f(prod), sum);
            wbar += WSTEP;

            const unsigned b0 = __ballot_sync(FULLMASK, (p.x > 0.5f) == (t.x > 0.5f));
            const unsigned b1 = __ballot_sync(FULLMASK, (p.y > 0.5f) == (t.y > 0.5f));
            const unsigned b2 = __ballot_sync(FULLMASK, (p.z > 0.5f) == (t.z > 0.5f));
            const unsigned b3 = __ballot_sync(FULLMASK, (p.w > 0.5f) == (t.w > 0.5f));
            if (it == myIt) { r0 = b0; r1 = b1; r2 = b2; r3 = b3; }

            // refill this slot with stage g+DEPTH (data fully consumed above)
            const int gn = g + DEPTH;
            if (gn < T) {
                const int cn = b + (gn >> 2) * GRID;
                const size_t goff = (size_t)cn * CHUNK + thrOff + (gn & 3) * 128;
                cp_async16(my_p + so, pred + goff);
                cp_async16(my_t + so, tru + goff);
            }
            cp_commit();    // commit every stage (empty group near tail is fine)

            if (++slot == DEPTH) slot = 0;
        }

        // ---- per-chunk finalize (loads for next chunks stay in flight) ----
        const int shq = (lane & 7) << 2;
        const unsigned m =  spread8((r0 >> shq) & 0xFu)
                         | (spread8((r1 >> shq) & 0xFu) << 1)
                         | (spread8((r2 >> shq) & 0xFu) << 2)
                         | (spread8((r3 >> shq) & 0xFu) << 3);

        const unsigned nmask = (~m) & 0xFFFFu;
        int pref = nmask ? (__ffs((int)nmask) - 1) : 16;
        int suff = nmask ? __clz((int)(nmask << 16)) : 16;
        int mx = 0;
        {
            unsigned x = m;
            while (x) { x &= (x << 1); ++mx; }
        }

        int lenA = 16;
#pragma unroll
        for (int s = 1; s < 32; s <<= 1) {
            const int prefB = __shfl_down_sync(FULLMASK, pref, s);
            const int mxB   = __shfl_down_sync(FULLMASK, mx,   s);
            const int suffB = __shfl_down_sync(FULLMASK, suff, s);
            const bool allA = (pref == lenA);
            const bool allB = (prefB == lenA);
            const int nmx = max(max(mx, mxB), suff + prefB);
            const int np  = allA ? (lenA + prefB) : pref;
            const int ns  = allB ? (lenA + suff) : suffB;
            pref = np; mx = nmx; suff = ns;
            lenA <<= 1;
        }

#pragma unroll
        for (int s = 16; s > 0; s >>= 1)
            sum += __shfl_down_sync(FULLMASK, sum, s);

        if (lane == 0) {
            s_sum[warp]  = sum;
            s_pref[warp] = pref;
            s_mx[warp]   = mx;
            s_suff[warp] = suff;
        }
        __syncthreads();

        if (tid == 0) {
            float bs = 0.0f;
            int bp = 0, bm = 0, bsf = 0, bl = 0;
#pragma unroll
            for (int w = 0; w < WARPS; ++w) {
                bs += s_sum[w];
                seg_combine(bp, bm, bsf, bl, s_pref[w], s_mx[w], s_suff[w], WARP_ELEMS);
            }
            g_sum[c]  = bs;
            g_pref[c] = bp;
            g_mx[c]   = bm;
            g_suff[c] = bsf;
        }
        __syncthreads();   // protect s_* reuse next chunk
    }

    // ---- last-block-done final combine (one block, fixed order -> deterministic)
    __shared__ bool isLast;
    __threadfence();
    if (tid == 0) {
        const unsigned prev = atomicAdd(&g_count, 1u);
        isLast = (prev == gridDim.x - 1);
    }
    __syncthreads();
    if (!isLast) return;

    {
        // reuse the (now dead) ring smem for the combine arrays
        float* sh_sum  = (float*)ring;                  // [THREADS]
        int*   sh_pref = (int*)(ring + THREADS * 4);
        int*   sh_mx   = (int*)(ring + THREADS * 8);
        int*   sh_suff = (int*)(ring + THREADS * 12);
        int*   sh_len  = (int*)(ring + THREADS * 16);

        const int t = tid;
        const int per = (NCH + THREADS - 1) / THREADS;   // 16
        const int lo = t * per;
        const int hi = min(lo + per, NCH);

        float fs = 0.0f;
        int fp = 0, fm = 0, fsf = 0, fl = 0;
        for (int i = lo; i < hi; ++i) {
            fs += g_sum[i];
            seg_combine(fp, fm, fsf, fl, g_pref[i], g_mx[i], g_suff[i], CHUNK);
        }
        sh_sum[t] = fs; sh_pref[t] = fp; sh_mx[t] = fm; sh_suff[t] = fsf; sh_len[t] = fl;
        __syncthreads();

        for (int s = 1; s < THREADS; s <<= 1) {
            if ((t & (2 * s - 1)) == 0) {
                sh_sum[t] += sh_sum[t + s];
                int p = sh_pref[t], m2 = sh_mx[t], sf = sh_suff[t], L = sh_len[t];
                seg_combine(p, m2, sf, L,
                            sh_pref[t + s], sh_mx[t + s], sh_suff[t + s], sh_len[t + s]);
                sh_pref[t] = p; sh_mx[t] = m2; sh_suff[t] = sf; sh_len[t] = L;
            }
            __syncthreads();
        }

        if (t == 0) {
            const float wbce = (-LN2F * sh_sum[0]) / (float)n;
            const float cwl  = 1.0f - (float)sh_mx[0] / (float)n;
            out[0] = 0.5f * wbce + 0.5f * cwl;
            g_count = 0;
        }
    }
}

extern "C" void kernel_launch(void* const* d_in, const int* in_sizes, int n_in,
                              void* d_out, int out_size) {
    const float* y_pred = (const float*)d_in[0];
    const float* y_true = (const float*)d_in[1];
    float* out = (float*)d_out;
    const int n = in_sizes[0];          // 16777216

    int dev = 0, sms = 148;
    cudaGetDevice(&dev);
    cudaDeviceGetAttribute(&sms, cudaDevAttrMultiProcessorCount, dev);
    const int grid = sms * 4;           // one wave at 4 blocks/SM (48 KB ring)

    cudaFuncSetAttribute(fused_kernel,
                         cudaFuncAttributeMaxDynamicSharedMemorySize, SMEM_BYTES);
    fused_kernel<<<grid, THREADS, SMEM_BYTES>>>(y_pred, y_true, out, n);
}

// round 12
// speedup vs baseline: 1.1308x; 1.1308x over previous
#include <cuda_runtime.h>
#include <math.h>
#include <stdint.h>

// out = 0.5 * mean(dw * bce) + 0.5 * (1 - max_correct_streak / N)
//   bce_i = -log( (1+eps) - |t_i - p_i| )   (t exactly 0/1)
//   correct_i = (p_i > 0.5) == (t_i > 0.5)
//   dw_i = (i+1)/2^24  -- computed, not loaded.
//
// R12 = R8 (best verified: cp.async per-thread 4-stage pipeline, CHUNK 4096,
// one __log2f per 4 elems, branchless |t-p| BCE, ballot bits -> 16-bit lane
// masks, one order-preserving shfl tree, last-block-done deterministic finish)
// + .L2::256B prefetch modifier on the cp.async ops: each 16 B LDGSTS triggers
// a 256 B L2 fill, so neighboring threads' requests hit L2 and DRAM streams
// ahead of demand. Zero extra instructions/registers.

#define FULLMASK 0xFFFFFFFFu

static constexpr int THREADS    = 256;
static constexpr int WARPS      = THREADS / 32;
static constexpr int CHUNK      = 4096;              // elems per block
static constexpr int WARP_ELEMS = CHUNK / WARPS;     // 512
static constexpr int ITERS      = WARP_ELEMS / 128;  // 4  (== pipeline depth)
static constexpr int MAXBLOCKS  = 4096;
static constexpr float EPSF     = 1e-6f;
static constexpr float LN2F     = 0.69314718055994531f;
static constexpr float INV_N    = 1.0f / 16777216.0f;   // 2^-24

static constexpr int STAGE_BYTES = THREADS * 32;     // 16 B p + 16 B t per thread
static constexpr int SMEM_BYTES  = ITERS * STAGE_BYTES;  // 32 KB

__device__ float    g_sum[MAXBLOCKS];
__device__ int      g_pref[MAXBLOCKS];
__device__ int      g_mx[MAXBLOCKS];
__device__ int      g_suff[MAXBLOCKS];
__device__ unsigned g_count = 0;   // reset by finishing block each replay

__device__ __forceinline__ void cp_async16_pf(uint32_t smem_addr, const void* gptr) {
    asm volatile("cp.async.cg.shared.global.L2::256B [%0], [%1], 16;"
                 :: "r"(smem_addr), "l"(gptr));
}
__device__ __forceinline__ void cp_commit() {
    asm volatile("cp.async.commit_group;");
}
template <int N>
__device__ __forceinline__ void cp_wait() {
    asm volatile("cp.async.wait_group %0;" :: "n"(N));
}
__device__ __forceinline__ float4 lds128(uint32_t a) {
    float4 v;
    asm volatile("ld.shared.v4.f32 {%0,%1,%2,%3}, [%4];"
                 : "=f"(v.x), "=f"(v.y), "=f"(v.z), "=f"(v.w) : "r"(a));
    return v;
}

__device__ __forceinline__ void seg_combine(int& pref, int& mx, int& suff, int& len,
                                            int prefB, int mxB, int suffB, int lenB) {
    const bool allA = (pref == len);
    const bool allB = (prefB == lenB);
    const int nm = max(max(mx, mxB), suff + prefB);
    const int np = allA ? (len + prefB) : pref;
    const int ns = allB ? (lenB + suff) : suffB;
    pref = np; mx = nm; suff = ns; len += lenB;
}

// Spread low 8 bits: source bit i -> position 4*i.
__device__ __forceinline__ unsigned spread8(unsigned x) {
    unsigned v = x & 0xFFu;
    v = (v | (v << 12)) & 0x000F000Fu;
    v = (v | (v << 6))  & 0x03030303u;
    v = (v | (v << 3))  & 0x11111111u;
    return v;
}

__global__ __launch_bounds__(THREADS, 6)
void fused_kernel(const float4* __restrict__ pred,
                  const float4* __restrict__ tru,
                  float* __restrict__ out, int n) {
    __shared__ __align__(16) char smem[SMEM_BYTES];

    const int tid  = threadIdx.x;
    const int lane = tid & 31;
    const int warp = tid >> 5;
    const int base4 = blockIdx.x * (CHUNK / 4) + warp * (WARP_ELEMS / 4) + lane;
    const int myIt = lane >> 3;     // iteration whose 4 ballots this lane captures

    const uint32_t smem_base = (uint32_t)__cvta_generic_to_shared(smem);
    const uint32_t my_p = smem_base + tid * 16;
    const uint32_t my_t = my_p + THREADS * 16;

    // ---- prologue: prefetch the whole chunk, one commit group per stage
#pragma unroll
    for (int s = 0; s < ITERS; ++s) {
        const uint32_t st = (uint32_t)(s * STAGE_BYTES);
        cp_async16_pf(my_p + st, pred + base4 + s * 32);
        cp_async16_pf(my_t + st, tru  + base4 + s * 32);
        cp_commit();
    }

    // per-iter group weight: mean of the 4 element weights = (4*idx4 + 2.5)/2^24
    float wbar = ((float)(base4 * 4) + 2.5f) * INV_N;
    const float WSTEP = 128.0f * INV_N;
    const float ONEPE = 1.0f + EPSF;

    float sum = 0.0f;                 // sum of wbar * log2(prod)
    unsigned r0 = 0, r1 = 0, r2 = 0, r3 = 0;

#pragma unroll
    for (int it = 0; it < ITERS; ++it) {
        if      (it == 0) cp_wait<3>();
        else if (it == 1) cp_wait<2>();
        else if (it == 2) cp_wait<1>();
        else              cp_wait<0>();

        const uint32_t st = (uint32_t)(it * STAGE_BYTES);
        const float4 p = lds128(my_p + st);
        const float4 t = lds128(my_t + st);

        // x_j = (1+eps) - |t_j - p_j|
        const float x0 = ONEPE - fabsf(t.x - p.x);
        const float x1 = ONEPE - fabsf(t.y - p.y);
        const float x2 = ONEPE - fabsf(t.z - p.z);
        const float x3 = ONEPE - fabsf(t.w - p.w);

        const float prod = (x0 * x1) * (x2 * x3);   // >= 1e-24, no underflow
        sum = fmaf(wbar, __log2f(prod), sum);
        wbar += WSTEP;

        const unsigned b0 = __ballot_sync(FULLMASK, (p.x > 0.5f) == (t.x > 0.5f));
        const unsigned b1 = __ballot_sync(FULLMASK, (p.y > 0.5f) == (t.y > 0.5f));
        const unsigned b2 = __ballot_sync(FULLMASK, (p.z > 0.5f) == (t.z > 0.5f));
        const unsigned b3 = __ballot_sync(FULLMASK, (p.w > 0.5f) == (t.w > 0.5f));
        if (it == myIt) { r0 = b0; r1 = b1; r2 = b2; r3 = b3; }
    }

    // ---- contiguous 16-bit lane mask: bit k = correct[16*lane + k] of warp chunk.
    const int shq = (lane & 7) << 2;
    const unsigned m =  spread8((r0 >> shq) & 0xFu)
                     | (spread8((r1 >> shq) & 0xFu) << 1)
                     | (spread8((r2 >> shq) & 0xFu) << 2)
                     | (spread8((r3 >> shq) & 0xFu) << 3);

    // ---- per-lane streak summary over 16 contiguous elements
    const unsigned nmask = (~m) & 0xFFFFu;
    int pref = nmask ? (__ffs((int)nmask) - 1) : 16;          // trailing ones
    int suff = nmask ? __clz((int)(nmask << 16)) : 16;        // leading ones of 16
    int mx = 0;
    {
        unsigned x = m;
        while (x) { x &= (x << 1); ++mx; }
    }

    // ---- ONE order-preserving warp tree reduce (adjacent pairs, ascending strides)
    int lenA = 16;
#pragma unroll
    for (int s = 1; s < 32; s <<= 1) {
        const int prefB = __shfl_down_sync(FULLMASK, pref, s);
        const int mxB   = __shfl_down_sync(FULLMASK, mx,   s);
        const int suffB = __shfl_down_sync(FULLMASK, suff, s);
        const bool allA = (pref == lenA);
        const bool allB = (prefB == lenA);
        const int nmx = max(max(mx, mxB), suff + prefB);
        const int np  = allA ? (lenA + prefB) : pref;
        const int ns  = allB ? (lenA + suff) : suffB;
        pref = np; mx = nmx; suff = ns;
        lenA <<= 1;
    }

    // ---- warp sum reduce
#pragma unroll
    for (int s = 16; s > 0; s >>= 1)
        sum += __shfl_down_sync(FULLMASK, sum, s);

    // ---- block combine (warps in order)
    __shared__ float s_sum[WARPS];
    __shared__ int s_pref[WARPS], s_mx[WARPS], s_suff[WARPS];
    if (lane == 0) {
        s_sum[warp]  = sum;
        s_pref[warp] = pref;
        s_mx[warp]   = mx;
        s_suff[warp] = suff;
    }
    __syncthreads();

    if (tid == 0) {
        float bs = 0.0f;
        int bp = 0, bm = 0, bsf = 0, bl = 0;
#pragma unroll
        for (int w = 0; w < WARPS; ++w) {
            bs += s_sum[w];
            seg_combine(bp, bm, bsf, bl, s_pref[w], s_mx[w], s_suff[w], WARP_ELEMS);
        }
        g_sum[blockIdx.x]  = bs;
        g_pref[blockIdx.x] = bp;
        g_mx[blockIdx.x]   = bm;
        g_suff[blockIdx.x] = bsf;
    }

    // ---- last-block-done final combine (one block, fixed order -> deterministic)
    __shared__ bool isLast;
    __threadfence();
    if (tid == 0) {
        const unsigned prev = atomicAdd(&g_count, 1u);
        isLast = (prev == gridDim.x - 1);
    }
    __syncthreads();
    if (!isLast) return;

    {
        __shared__ float sh_sum[THREADS];
        __shared__ int sh_pref[THREADS], sh_mx[THREADS], sh_suff[THREADS], sh_len[THREADS];

        const int t = tid;
        const int nblocks = gridDim.x;
        const int per = (nblocks + THREADS - 1) / THREADS;   // 4096/256 = 16
        const int lo = t * per;
        const int hi = min(lo + per, nblocks);

        float fs = 0.0f;
        int fp = 0, fm = 0, fsf = 0, fl = 0;
        for (int i = lo; i < hi; ++i) {
            fs += g_sum[i];
            seg_combine(fp, fm, fsf, fl, g_pref[i], g_mx[i], g_suff[i], CHUNK);
        }
        sh_sum[t] = fs; sh_pref[t] = fp; sh_mx[t] = fm; sh_suff[t] = fsf; sh_len[t] = fl;
        __syncthreads();

        for (int s = 1; s < THREADS; s <<= 1) {
            if ((t & (2 * s - 1)) == 0) {
                sh_sum[t] += sh_sum[t + s];
                int p = sh_pref[t], m2 = sh_mx[t], sf = sh_suff[t], L = sh_len[t];
                seg_combine(p, m2, sf, L,
                            sh_pref[t + s], sh_mx[t + s], sh_suff[t + s], sh_len[t + s]);
                sh_pref[t] = p; sh_mx[t] = m2; sh_suff[t] = sf; sh_len[t] = L;
            }
            __syncthreads();
        }

        if (t == 0) {
            const float wbce = (-LN2F * sh_sum[0]) / (float)n;
            const float cwl  = 1.0f - (float)sh_mx[0] / (float)n;
            out[0] = 0.5f * wbce + 0.5f * cwl;
            g_count = 0;
        }
    }
}

extern "C" void kernel_launch(void* const* d_in, const int* in_sizes, int n_in,
                              void* d_out, int out_size) {
    const float* y_pred = (const float*)d_in[0];
    const float* y_true = (const float*)d_in[1];
    float* out = (float*)d_out;
    const int n = in_sizes[0];          // 16777216
    const int grid = n / CHUNK;         // 4096

    fused_kernel<<<grid, THREADS>>>((const float4*)y_pred, (const float4*)y_true,
                                    out, n);
}

// round 13
// speedup vs baseline: 1.1951x; 1.0569x over previous
#include <cuda_runtime.h>
#include <math.h>
#include <stdint.h>

// out = 0.5 * mean(dw * bce) + 0.5 * (1 - max_correct_streak / N)
//   bce_i = -log( (1+eps) - |t_i - p_i| )   (t exactly 0/1)
//   correct_i = (p_i > 0.5) == (t_i > 0.5)
//   dw_i = (i+1)/2^24  -- computed, not loaded.
//
// R13 = R8 mechanics with: CHUNK 8192 processed as 8 stages through the same
// 4-slot 32 KB smem ring (static unrolled refill, per-thread private bytes,
// compile-time wait counts) -> epilogue paid half as often with identical
// block shape; R5-verified 32-bit lane-mask capture (myIt=lane>>2); packed
// one-shfl-per-round segment tree (pref|mx|suff in 10-bit fields, all values
// <=512 at shfl points).

#define FULLMASK 0xFFFFFFFFu

static constexpr int THREADS    = 256;
static constexpr int WARPS      = THREADS / 32;       // 8
static constexpr int CHUNK      = 8192;               // elems per block
static constexpr int WARP_ELEMS = CHUNK / WARPS;      // 1024
static constexpr int ITERS      = WARP_ELEMS / 128;   // 8
static constexpr int SLOTS      = 4;                  // smem ring depth
static constexpr int MAXBLOCKS  = 4096;
static constexpr float EPSF     = 1e-6f;
static constexpr float LN2F     = 0.69314718055994531f;
static constexpr float INV_N    = 1.0f / 16777216.0f; // 2^-24

static constexpr int STAGE_BYTES = THREADS * 32;      // 16 B p + 16 B t per thread
static constexpr int SMEM_BYTES  = SLOTS * STAGE_BYTES;  // 32 KB

__device__ float    g_sum[MAXBLOCKS];
__device__ int      g_pref[MAXBLOCKS];
__device__ int      g_mx[MAXBLOCKS];
__device__ int      g_suff[MAXBLOCKS];
__device__ unsigned g_count = 0;   // reset by finishing block each replay

__device__ __forceinline__ void cp_async16(uint32_t smem_addr, const void* gptr) {
    asm volatile("cp.async.cg.shared.global.L2::256B [%0], [%1], 16;"
                 :: "r"(smem_addr), "l"(gptr));
}
__device__ __forceinline__ void cp_commit() {
    asm volatile("cp.async.commit_group;");
}
template <int N>
__device__ __forceinline__ void cp_wait() {
    asm volatile("cp.async.wait_group %0;" :: "n"(N));
}
__device__ __forceinline__ float4 lds128(uint32_t a) {
    float4 v;
    asm volatile("ld.shared.v4.f32 {%0,%1,%2,%3}, [%4];"
                 : "=f"(v.x), "=f"(v.y), "=f"(v.z), "=f"(v.w) : "r"(a));
    return v;
}

__device__ __forceinline__ void seg_combine(int& pref, int& mx, int& suff, int& len,
                                            int prefB, int mxB, int suffB, int lenB) {
    const bool allA = (pref == len);
    const bool allB = (prefB == lenB);
    const int nm = max(max(mx, mxB), suff + prefB);
    const int np = allA ? (len + prefB) : pref;
    const int ns = allB ? (lenB + suff) : suffB;
    pref = np; mx = nm; suff = ns; len += lenB;
}

// Spread low 8 bits: source bit i -> position 4*i.
__device__ __forceinline__ unsigned spread8(unsigned x) {
    unsigned v = x & 0xFFu;
    v = (v | (v << 12)) & 0x000F000Fu;
    v = (v | (v << 6))  & 0x03030303u;
    v = (v | (v << 3))  & 0x11111111u;
    return v;
}

__global__ __launch_bounds__(THREADS, 6)
void fused_kernel(const float4* __restrict__ pred,
                  const float4* __restrict__ tru,
                  float* __restrict__ out, int n) {
    __shared__ __align__(16) char smem[SMEM_BYTES];

    const int tid  = threadIdx.x;
    const int lane = tid & 31;
    const int warp = tid >> 5;
    const int base4 = blockIdx.x * (CHUNK / 4) + warp * (WARP_ELEMS / 4) + lane;
    const int myIt = lane >> 2;     // iteration whose 4 ballots this lane captures

    const uint32_t smem_base = (uint32_t)__cvta_generic_to_shared(smem);
    const uint32_t my_p = smem_base + tid * 16;
    const uint32_t my_t = my_p + THREADS * 16;

    // ---- prologue: stages 0..3 into slots 0..3
#pragma unroll
    for (int s = 0; s < SLOTS; ++s) {
        const uint32_t st = (uint32_t)(s * STAGE_BYTES);
        cp_async16(my_p + st, pred + base4 + s * 32);
        cp_async16(my_t + st, tru  + base4 + s * 32);
        cp_commit();
    }

    // per-iter group weight: mean of 4 element weights = (4*idx4 + 2.5)/2^24
    float wbar = ((float)(base4 * 4) + 2.5f) * INV_N;
    const float WSTEP = 128.0f * INV_N;
    const float ONEPE = 1.0f + EPSF;

    float sum = 0.0f;
    unsigned r0 = 0, r1 = 0, r2 = 0, r3 = 0;

#pragma unroll
    for (int it = 0; it < ITERS; ++it) {
        // static wait schedule: 3,3,3,3,3,2,1,0 pending allowed
        if      (it <= 4) cp_wait<3>();
        else if (it == 5) cp_wait<2>();
        else if (it == 6) cp_wait<1>();
        else              cp_wait<0>();

        const int slot = it & 3;
        const uint32_t st = (uint32_t)(slot * STAGE_BYTES);
        const float4 p = lds128(my_p + st);
        const float4 t = lds128(my_t + st);

        const float x0 = ONEPE - fabsf(t.x - p.x);
        const float x1 = ONEPE - fabsf(t.y - p.y);
        const float x2 = ONEPE - fabsf(t.z - p.z);
        const float x3 = ONEPE - fabsf(t.w - p.w);

        const float prod = (x0 * x1) * (x2 * x3);   // >= 1e-24, no underflow
        sum = fmaf(wbar, __log2f(prod), sum);
        wbar += WSTEP;

        const unsigned b0 = __ballot_sync(FULLMASK, (p.x > 0.5f) == (t.x > 0.5f));
        const unsigned b1 = __ballot_sync(FULLMASK, (p.y > 0.5f) == (t.y > 0.5f));
        const unsigned b2 = __ballot_sync(FULLMASK, (p.z > 0.5f) == (t.z > 0.5f));
        const unsigned b3 = __ballot_sync(FULLMASK, (p.w > 0.5f) == (t.w > 0.5f));
        if (it == myIt) { r0 = b0; r1 = b1; r2 = b2; r3 = b3; }

        // rolling refill: slot just consumed gets stage it+4 (own bytes, no sync)
        if (it < ITERS - SLOTS) {
            cp_async16(my_p + st, pred + base4 + (it + SLOTS) * 32);
            cp_async16(my_t + st, tru  + base4 + (it + SLOTS) * 32);
            cp_commit();
        }
    }

    // ---- contiguous 32-bit lane mask: bit k = correct[32*lane + k] of warp chunk
    // (R5-verified: lane L captured iteration L>>2, q = L&3; bit k comes from
    //  bit (8q + (k>>2)) of ballot word (k&3))
    const int shq = (lane & 3) << 3;
    const unsigned m =  spread8(r0 >> shq)
                     | (spread8(r1 >> shq) << 1)
                     | (spread8(r2 >> shq) << 2)
                     | (spread8(r3 >> shq) << 3);

    // ---- per-lane streak summary over 32 contiguous elements
    const unsigned nmask = ~m;
    int pref = nmask ? (__ffs((int)nmask) - 1) : 32;
    int suff = __clz((int)nmask);                 // 32 when nmask==0
    int mx = 0;
    {
        unsigned x = m;
        while (x) { x &= (x << 1); ++mx; }
    }

    // ---- packed one-shfl-per-round order-preserving tree.
    // fields: pref[0:10) | mx[10:20) | suff[20:30); all values <= 512 at
    // every shfl point (len going into the last round is 512).
    unsigned pk = (unsigned)pref | ((unsigned)mx << 10) | ((unsigned)suff << 20);
    int lenA = 32;
#pragma unroll
    for (int s = 1; s < 32; s <<= 1) {
        const unsigned pkB = __shfl_down_sync(FULLMASK, pk, s);
        const int prefA = (int)(pk & 0x3FFu);
        const int mxA   = (int)((pk >> 10) & 0x3FFu);
        const int suffA = (int)((pk >> 20) & 0x3FFu);
        const int prefB = (int)(pkB & 0x3FFu);
        const int mxB   = (int)((pkB >> 10) & 0x3FFu);
        const int suffB = (int)((pkB >> 20) & 0x3FFu);
        const bool allA = (prefA == lenA);
        const bool allB = (prefB == lenA);
        const int nmx = max(max(mxA, mxB), suffA + prefB);
        const int np  = allA ? (lenA + prefB) : prefA;
        const int ns  = allB ? (lenA + suffA) : suffB;
        pk = (unsigned)np | ((unsigned)nmx << 10) | ((unsigned)ns << 20);
        lenA <<= 1;
    }
    pref = (int)(pk & 0x3FFu);
    mx   = (int)((pk >> 10) & 0x3FFu);
    suff = (int)((pk >> 20) & 0x3FFu);

    // ---- warp sum reduce
#pragma unroll
    for (int s = 16; s > 0; s >>= 1)
        sum += __shfl_down_sync(FULLMASK, sum, s);

    // ---- block combine (warps in order)
    __shared__ float s_sum[WARPS];
    __shared__ int s_pref[WARPS], s_mx[WARPS], s_suff[WARPS];
    if (lane == 0) {
        s_sum[warp]  = sum;
        s_pref[warp] = pref;
        s_mx[warp]   = mx;
        s_suff[warp] = suff;
    }
    __syncthreads();

    if (tid == 0) {
        float bs = 0.0f;
        int bp = 0, bm = 0, bsf = 0, bl = 0;
#pragma unroll
        for (int w = 0; w < WARPS; ++w) {
            bs += s_sum[w];
            seg_combine(bp, bm, bsf, bl, s_pref[w], s_mx[w], s_suff[w], WARP_ELEMS);
        }
        g_sum[blockIdx.x]  = bs;
        g_pref[blockIdx.x] = bp;
        g_mx[blockIdx.x]   = bm;
        g_suff[blockIdx.x] = bsf;
    }

    // ---- last-block-done final combine (one block, fixed order -> deterministic)
    __shared__ bool isLast;
    __threadfence();
    if (tid == 0) {
        const unsigned prev = atomicAdd(&g_count, 1u);
        isLast = (prev == gridDim.x - 1);
    }
    __syncthreads();
    if (!isLast) return;

    {
        __shared__ float sh_sum[THREADS];
        __shared__ int sh_pref[THREADS], sh_mx[THREADS], sh_suff[THREADS], sh_len[THREADS];

        const int t = tid;
        const int nblocks = gridDim.x;
        const int per = (nblocks + THREADS - 1) / THREADS;   // 2048/256 = 8
        const int lo = t * per;
        const int hi = min(lo + per, nblocks);

        float fs = 0.0f;
        int fp = 0, fm = 0, fsf = 0, fl = 0;
        for (int i = lo; i < hi; ++i) {
            fs += g_sum[i];
            seg_combine(fp, fm, fsf, fl, g_pref[i], g_mx[i], g_suff[i], CHUNK);
        }
        sh_sum[t] = fs; sh_pref[t] = fp; sh_mx[t] = fm; sh_suff[t] = fsf; sh_len[t] = fl;
        __syncthreads();

        for (int s = 1; s < THREADS; s <<= 1) {
            if ((t & (2 * s - 1)) == 0) {
                sh_sum[t] += sh_sum[t + s];
                int p = sh_pref[t], m2 = sh_mx[t], sf = sh_suff[t], L = sh_len[t];
                seg_combine(p, m2, sf, L,
                            sh_pref[t + s], sh_mx[t + s], sh_suff[t + s], sh_len[t + s]);
                sh_pref[t] = p; sh_mx[t] = m2; sh_suff[t] = sf; sh_len[t] = L;
            }
            __syncthreads();
        }

        if (t == 0) {
            const float wbce = (-LN2F * sh_sum[0]) / (float)n;
            const float cwl  = 1.0f - (float)sh_mx[0] / (float)n;
            out[0] = 0.5f * wbce + 0.5f * cwl;
            g_count = 0;
        }
    }
}

extern "C" void kernel_launch(void* const* d_in, const int* in_sizes, int n_in,
                              void* d_out, int out_size) {
    const float* y_pred = (const float*)d_in[0];
    const float* y_true = (const float*)d_in[1];
    float* out = (float*)d_out;
    const int n = in_sizes[0];          // 16777216
    const int grid = n / CHUNK;         // 2048

    fused_kernel<<<grid, THREADS>>>((const float4*)y_pred, (const float4*)y_true,
                                    out, n);
}

// round 14
// speedup vs baseline: 1.2881x; 1.0778x over previous
#include <cuda_runtime.h>
#include <math.h>
#include <stdint.h>

// out = 0.5 * mean(dw * bce) + 0.5 * (1 - max_correct_streak / N)
//   bce_i = -log( (1+eps) - |t_i - p_i| )   (t exactly 0/1)
//   correct_i = (p_i > 0.5) == (t_i > 0.5)
//   dw_i = (i+1)/2^24  -- computed, not loaded.
//
// R14 = R13 (8-stage rolling cp.async ring, CHUNK 8192, one __log2f per
// 4 elems, 32-bit lane masks, packed 1-shfl/round tree, last-block finish)
// with SLOTS 4 -> 5 (40 KB ring) so occupancy drops to 5 blocks/SM:
// conc 740, grid 2048 -> 2.77 waves -> ceil 3 -> 92.3% wave efficiency
// (vs 77% at 6 blocks/SM), plus a deeper pipeline (up to 5 pending stages).
// Epilogue smem arrays overlay the dead ring to keep smem ~40 KB.

#define FULLMASK 0xFFFFFFFFu

static constexpr int THREADS    = 256;
static constexpr int WARPS      = THREADS / 32;       // 8
static constexpr int CHUNK      = 8192;               // elems per block
static constexpr int WARP_ELEMS = CHUNK / WARPS;      // 1024
static constexpr int ITERS      = WARP_ELEMS / 128;   // 8
static constexpr int SLOTS      = 5;                  // smem ring depth
static constexpr int MAXBLOCKS  = 4096;
static constexpr float EPSF     = 1e-6f;
static constexpr float LN2F     = 0.69314718055994531f;
static constexpr float INV_N    = 1.0f / 16777216.0f; // 2^-24

static constexpr int STAGE_BYTES = THREADS * 32;      // 8 KB (16 B p + 16 B t / thread)
static constexpr int SMEM_BYTES  = SLOTS * STAGE_BYTES;  // 40 KB

__device__ float    g_sum[MAXBLOCKS];
__device__ int      g_pref[MAXBLOCKS];
__device__ int      g_mx[MAXBLOCKS];
__device__ int      g_suff[MAXBLOCKS];
__device__ unsigned g_count = 0;   // reset by finishing block each replay

__device__ __forceinline__ void cp_async16(uint32_t smem_addr, const void* gptr) {
    asm volatile("cp.async.cg.shared.global.L2::256B [%0], [%1], 16;"
                 :: "r"(smem_addr), "l"(gptr));
}
__device__ __forceinline__ void cp_commit() {
    asm volatile("cp.async.commit_group;");
}
template <int N>
__device__ __forceinline__ void cp_wait() {
    asm volatile("cp.async.wait_group %0;" :: "n"(N));
}
__device__ __forceinline__ float4 lds128(uint32_t a) {
    float4 v;
    asm volatile("ld.shared.v4.f32 {%0,%1,%2,%3}, [%4];"
                 : "=f"(v.x), "=f"(v.y), "=f"(v.z), "=f"(v.w) : "r"(a));
    return v;
}

__device__ __forceinline__ void seg_combine(int& pref, int& mx, int& suff, int& len,
                                            int prefB, int mxB, int suffB, int lenB) {
    const bool allA = (pref == len);
    const bool allB = (prefB == lenB);
    const int nm = max(max(mx, mxB), suff + prefB);
    const int np = allA ? (len + prefB) : pref;
    const int ns = allB ? (lenB + suff) : suffB;
    pref = np; mx = nm; suff = ns; len += lenB;
}

// Spread low 8 bits: source bit i -> position 4*i.
__device__ __forceinline__ unsigned spread8(unsigned x) {
    unsigned v = x & 0xFFu;
    v = (v | (v << 12)) & 0x000F000Fu;
    v = (v | (v << 6))  & 0x03030303u;
    v = (v | (v << 3))  & 0x11111111u;
    return v;
}

__global__ __launch_bounds__(THREADS, 5)
void fused_kernel(const float4* __restrict__ pred,
                  const float4* __restrict__ tru,
                  float* __restrict__ out, int n) {
    __shared__ __align__(16) char ring[SMEM_BYTES];

    const int tid  = threadIdx.x;
    const int lane = tid & 31;
    const int warp = tid >> 5;
    const int base4 = blockIdx.x * (CHUNK / 4) + warp * (WARP_ELEMS / 4) + lane;
    const int myIt = lane >> 2;     // iteration whose 4 ballots this lane captures

    const uint32_t smem_base = (uint32_t)__cvta_generic_to_shared(ring);
    const uint32_t my_p = smem_base + tid * 16;
    const uint32_t my_t = my_p + THREADS * 16;

    // ---- prologue: stages 0..4 into slots 0..4 (5 real commit groups)
#pragma unroll
    for (int s = 0; s < SLOTS; ++s) {
        const uint32_t st = (uint32_t)(s * STAGE_BYTES);
        cp_async16(my_p + st, pred + base4 + s * 32);
        cp_async16(my_t + st, tru  + base4 + s * 32);
        cp_commit();
    }

    // per-iter group weight: mean of 4 element weights = (4*idx4 + 2.5)/2^24
    float wbar = ((float)(base4 * 4) + 2.5f) * INV_N;
    const float WSTEP = 128.0f * INV_N;
    const float ONEPE = 1.0f + EPSF;

    float sum = 0.0f;
    unsigned r0 = 0, r1 = 0, r2 = 0, r3 = 0;

    // Real commit groups only: 5 prologue + 3 refills = 8 (group g == stage g).
    // At iter it, committed = 5 + min(it,3); need groups 0..it done:
    // pending allowed = 4,4,4,4,3,2,1,0.
#pragma unroll
    for (int it = 0; it < ITERS; ++it) {
        if      (it <= 3) cp_wait<4>();
        else if (it == 4) cp_wait<3>();
        else if (it == 5) cp_wait<2>();
        else if (it == 6) cp_wait<1>();
        else              cp_wait<0>();

        const int slot = it % SLOTS;
        const uint32_t st = (uint32_t)(slot * STAGE_BYTES);
        const float4 p = lds128(my_p + st);
        const float4 t = lds128(my_t + st);

        const float x0 = ONEPE - fabsf(t.x - p.x);
        const float x1 = ONEPE - fabsf(t.y - p.y);
        const float x2 = ONEPE - fabsf(t.z - p.z);
        const float x3 = ONEPE - fabsf(t.w - p.w);

        const float prod = (x0 * x1) * (x2 * x3);   // >= 1e-24, no underflow
        sum = fmaf(wbar, __log2f(prod), sum);
        wbar += WSTEP;

        const unsigned b0 = __ballot_sync(FULLMASK, (p.x > 0.5f) == (t.x > 0.5f));
        const unsigned b1 = __ballot_sync(FULLMASK, (p.y > 0.5f) == (t.y > 0.5f));
        const unsigned b2 = __ballot_sync(FULLMASK, (p.z > 0.5f) == (t.z > 0.5f));
        const unsigned b3 = __ballot_sync(FULLMASK, (p.w > 0.5f) == (t.w > 0.5f));
        if (it == myIt) { r0 = b0; r1 = b1; r2 = b2; r3 = b3; }

        // rolling refill: slot just consumed gets stage it+5 (own bytes, no sync)
        if (it < ITERS - SLOTS) {   // it < 3
            cp_async16(my_p + st, pred + base4 + (it + SLOTS) * 32);
            cp_async16(my_t + st, tru  + base4 + (it + SLOTS) * 32);
            cp_commit();
        }
    }

    // ---- contiguous 32-bit lane mask: bit k = correct[32*lane + k] of warp chunk
    const int shq = (lane & 3) << 3;
    const unsigned m =  spread8(r0 >> shq)
                     | (spread8(r1 >> shq) << 1)
                     | (spread8(r2 >> shq) << 2)
                     | (spread8(r3 >> shq) << 3);

    // ---- per-lane streak summary over 32 contiguous elements
    const unsigned nmask = ~m;
    int pref = nmask ? (__ffs((int)nmask) - 1) : 32;
    int suff = __clz((int)nmask);                 // 32 when nmask==0
    int mx = 0;
    {
        unsigned x = m;
        while (x) { x &= (x << 1); ++mx; }
    }

    // ---- packed one-shfl-per-round order-preserving tree (fields 10 bits;
    // values <= 512 at every shfl point)
    unsigned pk = (unsigned)pref | ((unsigned)mx << 10) | ((unsigned)suff << 20);
    int lenA = 32;
#pragma unroll
    for (int s = 1; s < 32; s <<= 1) {
        const unsigned pkB = __shfl_down_sync(FULLMASK, pk, s);
        const int prefA = (int)(pk & 0x3FFu);
        const int mxA   = (int)((pk >> 10) & 0x3FFu);
        const int suffA = (int)((pk >> 20) & 0x3FFu);
        const int prefB = (int)(pkB & 0x3FFu);
        const int mxB   = (int)((pkB >> 10) & 0x3FFu);
        const int suffB = (int)((pkB >> 20) & 0x3FFu);
        const bool allA = (prefA == lenA);
        const bool allB = (prefB == lenA);
        const int nmx = max(max(mxA, mxB), suffA + prefB);
        const int np  = allA ? (lenA + prefB) : prefA;
        const int ns  = allB ? (lenA + suffA) : suffB;
        pk = (unsigned)np | ((unsigned)nmx << 10) | ((unsigned)ns << 20);
        lenA <<= 1;
    }
    pref = (int)(pk & 0x3FFu);
    mx   = (int)((pk >> 10) & 0x3FFu);
    suff = (int)((pk >> 20) & 0x3FFu);

    // ---- warp sum reduce
#pragma unroll
    for (int s = 16; s > 0; s >>= 1)
        sum += __shfl_down_sync(FULLMASK, sum, s);

    // ---- block combine: overlay warp arrays on the dead ring
    float* s_sum  = (float*)ring;                       // [WARPS]
    int*   s_pref = (int*)(ring + 64);
    int*   s_mx   = (int*)(ring + 128);
    int*   s_suff = (int*)(ring + 192);
    __syncthreads();      // ensure all lds128 reads of ring data are done
    if (lane == 0) {
        s_sum[warp]  = sum;
        s_pref[warp] = pref;
        s_mx[warp]   = mx;
        s_suff[warp] = suff;
    }
    __syncthreads();

    if (tid == 0) {
        float bs = 0.0f;
        int bp = 0, bm = 0, bsf = 0, bl = 0;
#pragma unroll
        for (int w = 0; w < WARPS; ++w) {
            bs += s_sum[w];
            seg_combine(bp, bm, bsf, bl, s_pref[w], s_mx[w], s_suff[w], WARP_ELEMS);
        }
        g_sum[blockIdx.x]  = bs;
        g_pref[blockIdx.x] = bp;
        g_mx[blockIdx.x]   = bm;
        g_suff[blockIdx.x] = bsf;
    }

    // ---- last-block-done final combine (one block, fixed order -> deterministic)
    __shared__ bool isLast;
    __threadfence();
    if (tid == 0) {
        const unsigned prev = atomicAdd(&g_count, 1u);
        isLast = (prev == gridDim.x - 1);
    }
    __syncthreads();
    if (!isLast) return;

    {
        // epilogue arrays overlay the ring past the warp arrays
        float* sh_sum  = (float*)(ring + 1024);                 // [THREADS]
        int*   sh_pref = (int*)(ring + 1024 + THREADS * 4);
        int*   sh_mx   = (int*)(ring + 1024 + THREADS * 8);
        int*   sh_suff = (int*)(ring + 1024 + THREADS * 12);
        int*   sh_len  = (int*)(ring + 1024 + THREADS * 16);

        const int t = tid;
        const int nblocks = gridDim.x;
        const int per = (nblocks + THREADS - 1) / THREADS;   // 2048/256 = 8
        const int lo = t * per;
        const int hi = min(lo + per, nblocks);

        float fs = 0.0f;
        int fp = 0, fm = 0, fsf = 0, fl = 0;
        for (int i = lo; i < hi; ++i) {
            fs += g_sum[i];
            seg_combine(fp, fm, fsf, fl, g_pref[i], g_mx[i], g_suff[i], CHUNK);
        }
        sh_sum[t] = fs; sh_pref[t] = fp; sh_mx[t] = fm; sh_suff[t] = fsf; sh_len[t] = fl;
        __syncthreads();

        for (int s = 1; s < THREADS; s <<= 1) {
            if ((t & (2 * s - 1)) == 0) {
                sh_sum[t] += sh_sum[t + s];
                int p = sh_pref[t], m2 = sh_mx[t], sf = sh_suff[t], L = sh_len[t];
                seg_combine(p, m2, sf, L,
                            sh_pref[t + s], sh_mx[t + s], sh_suff[t + s], sh_len[t + s]);
                sh_pref[t] = p; sh_mx[t] = m2; sh_suff[t] = sf; sh_len[t] = L;
            }
            __syncthreads();
        }

        if (t == 0) {
            const float wbce = (-LN2F * sh_sum[0]) / (float)n;
            const float cwl  = 1.0f - (float)sh_mx[0] / (float)n;
            out[0] = 0.5f * wbce + 0.5f * cwl;
            g_count = 0;
        }
    }
}

extern "C" void kernel_launch(void* const* d_in, const int* in_sizes, int n_in,
                              void* d_out, int out_size) {
    const float* y_pred = (const float*)d_in[0];
    const float* y_true = (const float*)d_in[1];
    float* out = (float*)d_out;
    const int n = in_sizes[0];          // 16777216
    const int grid = n / CHUNK;         // 2048

    fused_kernel<<<grid, THREADS>>>((const float4*)y_pred, (const float4*)y_true,
                                    out, n);
}